// round 5
// baseline (speedup 1.0000x reference)
#include <cuda_runtime.h>
#include <cuda_fp16.h>

#define N_USERS 100000
#define N_ITEMS 200000
#define N_NODESC 300000
#define EMB 64
#define NLAYERS 3
#define N_EDGESC 9600000
#define BATCHC 4096
#define NEG_SLOPE 0.2f

// transform tiling
#define TN 128          // nodes per block
#define TTHREADS 256

// ---------------- device scratch (no mallocs allowed) ----------------
__device__ float g_ego[N_NODESC * EMB];     // fp32 master node embeddings
__device__ uint2 g_egoH[N_NODESC * 16];     // fp16 mirror (4 halfs per uint2) for gathers
__device__ float g_neigh[N_NODESC * EMB];   // aggregated neighbor embeddings
__device__ int   g_cnt[N_NODESC];
__device__ int   g_rowptr[N_NODESC + 1];
__device__ int   g_cursor[N_NODESC];
__device__ int2  g_cedge[N_EDGESC];         // packed (col, val-bits)
__device__ int   g_bsum[512];

// ---------------- f32x2 helpers (sm_103a packed fp32) ----------------
__device__ __forceinline__ void fma2(unsigned long long& d, unsigned long long a,
                                     unsigned long long b) {
    asm("fma.rn.f32x2 %0, %1, %2, %0;" : "+l"(d) : "l"(a), "l"(b));
}
__device__ __forceinline__ unsigned long long pk2(float lo, float hi) {
    unsigned long long r;
    asm("mov.b64 %0, {%1, %2};" : "=l"(r) : "f"(lo), "f"(hi));
    return r;
}
__device__ __forceinline__ float2 upk2(unsigned long long v) {
    float lo, hi;
    asm("mov.b64 {%0, %1}, %2;" : "=f"(lo), "=f"(hi) : "l"(v));
    return make_float2(lo, hi);
}

// ---------------- CSR build ----------------
__global__ void zero_cnt_kernel() {
    int i = blockIdx.x * blockDim.x + threadIdx.x;
    if (i < N_NODESC) g_cnt[i] = 0;
}

__global__ void hist_kernel(const int* __restrict__ row) {
    int e = blockIdx.x * blockDim.x + threadIdx.x;
    if (e < N_EDGESC) atomicAdd(&g_cnt[row[e]], 1);
}

__global__ void scan1_kernel() {
    __shared__ int s[1024];
    int t = threadIdx.x;
    int i = blockIdx.x * 1024 + t;
    int v = (i < N_NODESC) ? g_cnt[i] : 0;
    s[t] = v;
    __syncthreads();
#pragma unroll
    for (int off = 1; off < 1024; off <<= 1) {
        int x = (t >= off) ? s[t - off] : 0;
        __syncthreads();
        s[t] += x;
        __syncthreads();
    }
    if (i < N_NODESC) g_rowptr[i + 1] = s[t];
    if (t == 1023) g_bsum[blockIdx.x] = s[1023];
}

__global__ void scan2_kernel(int nb) {
    __shared__ int s[512];
    int t = threadIdx.x;
    int v = (t < nb) ? g_bsum[t] : 0;
    s[t] = v;
    __syncthreads();
#pragma unroll
    for (int off = 1; off < 512; off <<= 1) {
        int x = (t >= off) ? s[t - off] : 0;
        __syncthreads();
        s[t] += x;
        __syncthreads();
    }
    if (t < nb) g_bsum[t] = s[t] - v;
}

__global__ void scan3_kernel() {
    int i = blockIdx.x * blockDim.x + threadIdx.x;
    if (i >= N_NODESC) return;
    int incl = g_rowptr[i + 1] + g_bsum[i >> 10];
    g_rowptr[i + 1] = incl;
    g_cursor[i] = incl - g_cnt[i];
    if (i == 0) g_rowptr[0] = 0;
}

__global__ void scatter_kernel(const int* __restrict__ row,
                               const int* __restrict__ col,
                               const float* __restrict__ val) {
    int e = blockIdx.x * blockDim.x + threadIdx.x;
    if (e >= N_EDGESC) return;
    int r = row[e];
    int p = atomicAdd(&g_cursor[r], 1);
    g_cedge[p] = make_int2(col[e], __float_as_int(val[e]));
}

// ---------------- embedding init (fp32 + fp16 mirror) ----------------
__global__ void copy_ego_kernel(const float4* __restrict__ ue,
                                const float4* __restrict__ ie) {
    int i = blockIdx.x * blockDim.x + threadIdx.x;
    if (i >= N_NODESC * (EMB / 4)) return;
    float4* ego4 = reinterpret_cast<float4*>(g_ego);
    const int ucount = N_USERS * (EMB / 4);
    float4 v = (i < ucount) ? ue[i] : ie[i - ucount];
    ego4[i] = v;
    __half2 h0 = __float22half2_rn(make_float2(v.x, v.y));
    __half2 h1 = __float22half2_rn(make_float2(v.z, v.w));
    uint2 p;
    p.x = *reinterpret_cast<unsigned*>(&h0);
    p.y = *reinterpret_cast<unsigned*>(&h1);
    g_egoH[i] = p;
}

// ---------------- aggregation: neigh = segment_sum(egoH[col]*val, row) ----------------
__global__ void aggregate_kernel() {
    int gid = blockIdx.x * blockDim.x + threadIdx.x;
    int node = gid >> 4;
    if (node >= N_NODESC) return;
    int g = gid & 15;
    float4* neigh4 = reinterpret_cast<float4*>(g_neigh);

    int beg = g_rowptr[node];
    int end = g_rowptr[node + 1];
    float4 acc = make_float4(0.f, 0.f, 0.f, 0.f);
#pragma unroll 4
    for (int e = beg; e < end; e++) {
        int2 ev = g_cedge[e];
        int c = ev.x;
        float v = __int_as_float(ev.y);
        uint2 p = g_egoH[c * 16 + g];
        float2 f0 = __half22float2(*reinterpret_cast<__half2*>(&p.x));
        float2 f1 = __half22float2(*reinterpret_cast<__half2*>(&p.y));
        acc.x += v * f0.x;
        acc.y += v * f0.y;
        acc.z += v * f1.x;
        acc.w += v * f1.y;
    }
    neigh4[node * 16 + g] = acc;
}

// ---------------- tiled transform (shuffle-free GEMM):
// ego = l2norm(leaky_relu(neigh@Wgc + (ego*neigh)@Wbi + bgc + bbi))
// Block: 256 threads, 128 nodes. Thread tile: 4 nodes x 8 cols, f32x2 (gc,bi) accums.
// Dynamic smem: sPx[128 nodes][66 ull] (px pairs, 2 pad) + sW[64][64 ull] + sb[64].
// ----------------
#define SPX_STRIDE 66   // ull per node row (64 + 2 pad, keeps 16B alignment: 528 B)

__global__ void __launch_bounds__(TTHREADS, 2)
transform_kernel(const float* __restrict__ Wgc,
                 const float* __restrict__ bgc,
                 const float* __restrict__ Wbi,
                 const float* __restrict__ bbi,
                 int layer) {
    extern __shared__ char dsm[];
    unsigned long long* sPx = reinterpret_cast<unsigned long long*>(dsm);                 // TN*66 ull
    unsigned long long* sW  = sPx + TN * SPX_STRIDE;                                      // 64*64 ull
    float* sb = reinterpret_cast<float*>(sW + EMB * EMB);                                 // 64 floats

    const int tid = threadIdx.x;
    const int base = blockIdx.x * TN;

    // stage interleaved weights: sW[k*64 + j] = (Wgc[k][j], Wbi[k][j])
    {
        const float* w1g = Wgc + layer * EMB * EMB;
        const float* w2g = Wbi + layer * EMB * EMB;
        float2* sWf2 = reinterpret_cast<float2*>(sW);
        for (int i = tid; i < EMB * EMB; i += TTHREADS)
            sWf2[i] = make_float2(w1g[i], w2g[i]);
        if (tid < EMB)
            sb[tid] = bgc[layer * EMB + tid] + bbi[layer * EMB + tid];
    }

    // stage px = (neigh, ego*neigh) pairs, node-major
    {
        const float4* ego4 = reinterpret_cast<const float4*>(g_ego);
        const float4* neigh4 = reinterpret_cast<const float4*>(g_neigh);
        float4* sPxF4 = reinterpret_cast<float4*>(sPx);
        for (int i = tid; i < TN * 16; i += TTHREADS) {
            int local = i >> 4;       // node 0..127
            int kq = i & 15;          // float4 quad 0..15
            int gn = base + local;
            float4 a, b;  // a = two px pairs for k=4kq..4kq+1 etc.
            if (gn < N_NODESC) {
                float4 n = neigh4[gn * 16 + kq];
                float4 e = ego4[gn * 16 + kq];
                a = make_float4(n.x, e.x * n.x, n.y, e.y * n.y);
                b = make_float4(n.z, e.z * n.z, n.w, e.w * n.w);
            } else {
                a = make_float4(0.f, 0.f, 0.f, 0.f);
                b = a;
            }
            // node row = local*528 bytes = local*33 float4; kq -> 2 float4
            sPxF4[local * (SPX_STRIDE / 2) + kq * 2]     = a;
            sPxF4[local * (SPX_STRIDE / 2) + kq * 2 + 1] = b;
        }
    }
    __syncthreads();

    const int g_n = tid >> 3;    // node group 0..31
    const int g_c = tid & 7;     // col group 0..7 -> cols 8*g_c..8*g_c+7
    const int n0 = g_n * 4;      // local node base
    const int c0 = g_c * 8;      // col base

    const unsigned long long* x0 = sPx + (n0 + 0) * SPX_STRIDE;
    const unsigned long long* x1 = sPx + (n0 + 1) * SPX_STRIDE;
    const unsigned long long* x2 = sPx + (n0 + 2) * SPX_STRIDE;
    const unsigned long long* x3 = sPx + (n0 + 3) * SPX_STRIDE;
    const unsigned long long* wbase = sW + c0;

    // accumulators: 4 nodes x 8 cols, init with (bias, 0)
    unsigned long long acc[4][8];
#pragma unroll
    for (int c = 0; c < 8; c++) {
        unsigned long long b = pk2(sb[c0 + c], 0.f);
        acc[0][c] = b; acc[1][c] = b; acc[2][c] = b; acc[3][c] = b;
    }

#pragma unroll 4
    for (int k = 0; k < EMB; k++) {
        unsigned long long a0 = x0[k];
        unsigned long long a1 = x1[k];
        unsigned long long a2 = x2[k];
        unsigned long long a3 = x3[k];
        const unsigned long long* wr = wbase + k * EMB;
#pragma unroll
        for (int c = 0; c < 8; c++) {
            unsigned long long w = wr[c];
            fma2(acc[0][c], a0, w);
            fma2(acc[1][c], a1, w);
            fma2(acc[2][c], a2, w);
            fma2(acc[3][c], a3, w);
        }
    }

    // epilogue per node: combine halves, leaky, l2-norm (8 threads share a node), store
    const unsigned mask = 0xffffffffu;
#pragma unroll
    for (int j = 0; j < 4; j++) {
        int gn = base + n0 + j;
        float o[8];
        float s = 0.f;
#pragma unroll
        for (int c = 0; c < 8; c++) {
            float2 t = upk2(acc[j][c]);
            float v = t.x + t.y;
            v = (v >= 0.f) ? v : NEG_SLOPE * v;
            o[c] = v;
            s += v * v;
        }
        s += __shfl_xor_sync(mask, s, 1, 8);
        s += __shfl_xor_sync(mask, s, 2, 8);
        s += __shfl_xor_sync(mask, s, 4, 8);
        float sc = 1.0f / fmaxf(sqrtf(s), 1e-12f);

        if (gn < N_NODESC) {
            float4 v0 = make_float4(o[0] * sc, o[1] * sc, o[2] * sc, o[3] * sc);
            float4 v1 = make_float4(o[4] * sc, o[5] * sc, o[6] * sc, o[7] * sc);
            float4* outr = reinterpret_cast<float4*>(g_ego + gn * EMB + c0);
            outr[0] = v0;
            outr[1] = v1;
            __half2 h0 = __float22half2_rn(make_float2(v0.x, v0.y));
            __half2 h1 = __float22half2_rn(make_float2(v0.z, v0.w));
            __half2 h2 = __float22half2_rn(make_float2(v1.x, v1.y));
            __half2 h3 = __float22half2_rn(make_float2(v1.z, v1.w));
            uint4 hp;
            hp.x = *reinterpret_cast<unsigned*>(&h0);
            hp.y = *reinterpret_cast<unsigned*>(&h1);
            hp.z = *reinterpret_cast<unsigned*>(&h2);
            hp.w = *reinterpret_cast<unsigned*>(&h3);
            *reinterpret_cast<uint4*>(reinterpret_cast<char*>(g_egoH) + gn * 128 + g_c * 16) = hp;
        }
    }
}

// ---------------- output gather for one stage ----------------
__global__ void gather_out_kernel(const int* __restrict__ users,
                                  const int* __restrict__ pos,
                                  const int* __restrict__ neg,
                                  float* __restrict__ out,
                                  int stage) {
    int gid = blockIdx.x * blockDim.x + threadIdx.x;
    int r = gid >> 4;
    if (r >= 3 * BATCHC) return;
    int g = gid & 15;
    int node;
    if (r < BATCHC) node = users[r];
    else if (r < 2 * BATCHC) node = N_USERS + pos[r - BATCHC];
    else node = N_USERS + neg[r - 2 * BATCHC];

    const float4* ego4 = reinterpret_cast<const float4*>(g_ego);
    float4 v = ego4[node * 16 + g];
    *reinterpret_cast<float4*>(&out[(size_t)r * (4 * EMB) + stage * EMB + g * 4]) = v;
}

// ---------------- launch ----------------
extern "C" void kernel_launch(void* const* d_in, const int* in_sizes, int n_in,
                              void* d_out, int out_size) {
    const int*   edge_row = (const int*)d_in[0];
    const int*   edge_col = (const int*)d_in[1];
    const float* edge_val = (const float*)d_in[2];
    const float* user_emb = (const float*)d_in[3];
    const float* item_emb = (const float*)d_in[4];
    const float* W_gc     = (const float*)d_in[5];
    const float* b_gc     = (const float*)d_in[6];
    const float* W_bi     = (const float*)d_in[7];
    const float* b_bi     = (const float*)d_in[8];
    const int*   users    = (const int*)d_in[9];
    const int*   pos      = (const int*)d_in[10];
    const int*   neg      = (const int*)d_in[11];
    float* out = (float*)d_out;

    const int T = 256;
    const int nbNodes = (N_NODESC + T - 1) / T;
    const int nbEdges = (N_EDGESC + T - 1) / T;
    const int scanBlocks = (N_NODESC + 1023) / 1024;   // 293
    const int nbNode16 = (N_NODESC * 16) / T;          // 18750 (exact)
    const int nbGather = (3 * BATCHC * 16 + T - 1) / T;
    const int nbTrans = (N_NODESC + TN - 1) / TN;      // 2344

    // dynamic smem for transform: sPx + sW + sb
    const int smemBytes = TN * SPX_STRIDE * 8 + EMB * EMB * 8 + EMB * 4;  // 100,864 B
    static int attrDone = 0;
    cudaFuncSetAttribute(transform_kernel, cudaFuncAttributeMaxDynamicSharedMemorySize,
                         smemBytes);
    (void)attrDone;

    // CSR build
    zero_cnt_kernel<<<nbNodes, T>>>();
    hist_kernel<<<nbEdges, T>>>(edge_row);
    scan1_kernel<<<scanBlocks, 1024>>>();
    scan2_kernel<<<1, 512>>>(scanBlocks);
    scan3_kernel<<<nbNodes, T>>>();
    scatter_kernel<<<nbEdges, T>>>(edge_row, edge_col, edge_val);

    // init ego (fp32 + fp16 mirror)
    copy_ego_kernel<<<nbNode16, T>>>((const float4*)user_emb, (const float4*)item_emb);

    // stage 0 output
    gather_out_kernel<<<nbGather, T>>>(users, pos, neg, out, 0);

    // 3 layers
    for (int k = 0; k < NLAYERS; k++) {
        aggregate_kernel<<<nbNode16, T>>>();
        transform_kernel<<<nbTrans, TTHREADS, smemBytes>>>(W_gc, b_gc, W_bi, b_bi, k);
        gather_out_kernel<<<nbGather, T>>>(users, pos, neg, out, k + 1);
    }
}

// round 6
// speedup vs baseline: 1.2494x; 1.2494x over previous
#include <cuda_runtime.h>
#include <cuda_fp16.h>

#define N_USERS 100000
#define N_ITEMS 200000
#define N_NODESC 300000
#define EMB 64
#define NLAYERS 3
#define N_EDGESC 9600000
#define BATCHC 4096
#define NEG_SLOPE 0.2f

// transform tiling: 256 threads, 64 nodes/block, thread tile = 2 nodes x 8 cols
#define TN 64
#define TTHREADS 256
#define SPX_STRIDE 66   // ull per node row (64 + 2 pad) -> 528 B, 8-bank shift per 2 nodes
#define WCH_STRIDE 514  // ull per weight chunk (512 + 2 pad) -> 4112 B, 4-bank shift per chunk

// ---------------- device scratch (no mallocs allowed) ----------------
__device__ float g_ego[N_NODESC * EMB];     // fp32 master node embeddings
__device__ uint2 g_egoH[N_NODESC * 16];     // fp16 mirror (4 halfs per uint2) for gathers
__device__ float g_neigh[N_NODESC * EMB];   // aggregated neighbor embeddings
__device__ int   g_cnt[N_NODESC];
__device__ int   g_rowptr[N_NODESC + 1];
__device__ int   g_cursor[N_NODESC];
__device__ int2  g_cedge[N_EDGESC];         // packed (col, val-bits)
__device__ int   g_bsum[512];

// ---------------- f32x2 helpers (sm_103a packed fp32) ----------------
__device__ __forceinline__ void fma2(unsigned long long& d, unsigned long long a,
                                     unsigned long long b) {
    asm("fma.rn.f32x2 %0, %1, %2, %0;" : "+l"(d) : "l"(a), "l"(b));
}
__device__ __forceinline__ unsigned long long pk2(float lo, float hi) {
    unsigned long long r;
    asm("mov.b64 %0, {%1, %2};" : "=l"(r) : "f"(lo), "f"(hi));
    return r;
}
__device__ __forceinline__ float2 upk2(unsigned long long v) {
    float lo, hi;
    asm("mov.b64 {%0, %1}, %2;" : "=f"(lo), "=f"(hi) : "l"(v));
    return make_float2(lo, hi);
}

// ---------------- CSR build ----------------
__global__ void zero_cnt_kernel() {
    int i = blockIdx.x * blockDim.x + threadIdx.x;
    if (i < N_NODESC) g_cnt[i] = 0;
}

__global__ void hist_kernel(const int* __restrict__ row) {
    int e = blockIdx.x * blockDim.x + threadIdx.x;
    if (e < N_EDGESC) atomicAdd(&g_cnt[row[e]], 1);
}

__global__ void scan1_kernel() {
    __shared__ int s[1024];
    int t = threadIdx.x;
    int i = blockIdx.x * 1024 + t;
    int v = (i < N_NODESC) ? g_cnt[i] : 0;
    s[t] = v;
    __syncthreads();
#pragma unroll
    for (int off = 1; off < 1024; off <<= 1) {
        int x = (t >= off) ? s[t - off] : 0;
        __syncthreads();
        s[t] += x;
        __syncthreads();
    }
    if (i < N_NODESC) g_rowptr[i + 1] = s[t];
    if (t == 1023) g_bsum[blockIdx.x] = s[1023];
}

__global__ void scan2_kernel(int nb) {
    __shared__ int s[512];
    int t = threadIdx.x;
    int v = (t < nb) ? g_bsum[t] : 0;
    s[t] = v;
    __syncthreads();
#pragma unroll
    for (int off = 1; off < 512; off <<= 1) {
        int x = (t >= off) ? s[t - off] : 0;
        __syncthreads();
        s[t] += x;
        __syncthreads();
    }
    if (t < nb) g_bsum[t] = s[t] - v;
}

__global__ void scan3_kernel() {
    int i = blockIdx.x * blockDim.x + threadIdx.x;
    if (i >= N_NODESC) return;
    int incl = g_rowptr[i + 1] + g_bsum[i >> 10];
    g_rowptr[i + 1] = incl;
    g_cursor[i] = incl - g_cnt[i];
    if (i == 0) g_rowptr[0] = 0;
}

__global__ void scatter_kernel(const int* __restrict__ row,
                               const int* __restrict__ col,
                               const float* __restrict__ val) {
    int e = blockIdx.x * blockDim.x + threadIdx.x;
    if (e >= N_EDGESC) return;
    int r = row[e];
    int p = atomicAdd(&g_cursor[r], 1);
    g_cedge[p] = make_int2(col[e], __float_as_int(val[e]));
}

// ---------------- embedding init (fp32 + fp16 mirror) ----------------
__global__ void copy_ego_kernel(const float4* __restrict__ ue,
                                const float4* __restrict__ ie) {
    int i = blockIdx.x * blockDim.x + threadIdx.x;
    if (i >= N_NODESC * (EMB / 4)) return;
    float4* ego4 = reinterpret_cast<float4*>(g_ego);
    const int ucount = N_USERS * (EMB / 4);
    float4 v = (i < ucount) ? ue[i] : ie[i - ucount];
    ego4[i] = v;
    __half2 h0 = __float22half2_rn(make_float2(v.x, v.y));
    __half2 h1 = __float22half2_rn(make_float2(v.z, v.w));
    uint2 p;
    p.x = *reinterpret_cast<unsigned*>(&h0);
    p.y = *reinterpret_cast<unsigned*>(&h1);
    g_egoH[i] = p;
}

// ---------------- aggregation: neigh = segment_sum(egoH[col]*val, row) ----------------
__global__ void aggregate_kernel() {
    int gid = blockIdx.x * blockDim.x + threadIdx.x;
    int node = gid >> 4;
    if (node >= N_NODESC) return;
    int g = gid & 15;
    float4* neigh4 = reinterpret_cast<float4*>(g_neigh);

    int beg = g_rowptr[node];
    int end = g_rowptr[node + 1];
    float4 acc = make_float4(0.f, 0.f, 0.f, 0.f);
#pragma unroll 4
    for (int e = beg; e < end; e++) {
        int2 ev = g_cedge[e];
        int c = ev.x;
        float v = __int_as_float(ev.y);
        uint2 p = g_egoH[c * 16 + g];
        float2 f0 = __half22float2(*reinterpret_cast<__half2*>(&p.x));
        float2 f1 = __half22float2(*reinterpret_cast<__half2*>(&p.y));
        acc.x += v * f0.x;
        acc.y += v * f0.y;
        acc.z += v * f1.x;
        acc.w += v * f1.y;
    }
    neigh4[node * 16 + g] = acc;
}

// ---------------- tiled transform v2 (conflict-free, small reg tile):
// ego = l2norm(leaky_relu(neigh@Wgc + (ego*neigh)@Wbi + bgc + bbi))
// Block: 256 threads, 64 nodes. Thread: 2 nodes x 8 cols, f32x2 (gc,bi) accums.
// smem: sPx[64][66 ull] + sWc[8 chunks][514 ull] + sb[64]  (~67 KB)
// Weight chunk-major layout -> every LDS in the mainloop is bank-conflict-free.
// ----------------
__global__ void __launch_bounds__(TTHREADS)
transform_kernel(const float* __restrict__ Wgc,
                 const float* __restrict__ bgc,
                 const float* __restrict__ Wbi,
                 const float* __restrict__ bbi,
                 int layer) {
    extern __shared__ char dsm[];
    unsigned long long* sPx = reinterpret_cast<unsigned long long*>(dsm);   // TN*66
    unsigned long long* sWc = sPx + TN * SPX_STRIDE;                        // 8*514
    float* sb = reinterpret_cast<float*>(sWc + 8 * WCH_STRIDE);             // 64

    const int tid = threadIdx.x;
    const int base = blockIdx.x * TN;

    // stage weights chunk-major: sWc[c*514 + k*8 + i] = (Wgc[k][c*8+i], Wbi[k][c*8+i])
    {
        const float* w1g = Wgc + layer * EMB * EMB;
        const float* w2g = Wbi + layer * EMB * EMB;
        for (int i = tid; i < EMB * EMB; i += TTHREADS) {
            int k = i >> 6, j = i & 63;
            int c = j >> 3, ii = j & 7;
            sWc[c * WCH_STRIDE + k * 8 + ii] = pk2(w1g[i], w2g[i]);
        }
        if (tid < EMB)
            sb[tid] = bgc[layer * EMB + tid] + bbi[layer * EMB + tid];
    }

    // stage px = (neigh, ego*neigh) pairs, node-major
    {
        const float4* ego4 = reinterpret_cast<const float4*>(g_ego);
        const float4* neigh4 = reinterpret_cast<const float4*>(g_neigh);
        float4* sPxF4 = reinterpret_cast<float4*>(sPx);
        for (int i = tid; i < TN * 16; i += TTHREADS) {
            int local = i >> 4;       // node 0..63
            int kq = i & 15;          // float4 quad
            int gn = base + local;
            float4 a, b;
            if (gn < N_NODESC) {
                float4 n = neigh4[gn * 16 + kq];
                float4 e = ego4[gn * 16 + kq];
                a = make_float4(n.x, e.x * n.x, n.y, e.y * n.y);
                b = make_float4(n.z, e.z * n.z, n.w, e.w * n.w);
            } else {
                a = make_float4(0.f, 0.f, 0.f, 0.f);
                b = a;
            }
            sPxF4[local * (SPX_STRIDE / 2) + kq * 2]     = a;
            sPxF4[local * (SPX_STRIDE / 2) + kq * 2 + 1] = b;
        }
    }
    __syncthreads();

    const int g_n = tid >> 3;    // node group 0..31 (2 nodes each)
    const int g_c = tid & 7;     // col chunk 0..7
    const int n0 = g_n * 2;
    const int c0 = g_c * 8;

    const unsigned long long* xA = sPx + (n0 + 0) * SPX_STRIDE;
    const unsigned long long* xB = sPx + (n0 + 1) * SPX_STRIDE;
    const unsigned long long* wch = sWc + g_c * WCH_STRIDE;

    unsigned long long acc0[8], acc1[8];
#pragma unroll
    for (int c = 0; c < 8; c++) {
        unsigned long long b = pk2(sb[c0 + c], 0.f);
        acc0[c] = b;
        acc1[c] = b;
    }

#pragma unroll 4
    for (int k = 0; k < EMB; k++) {
        unsigned long long a0 = xA[k];
        unsigned long long a1 = xB[k];
        const unsigned long long* wr = wch + k * 8;
#pragma unroll
        for (int c = 0; c < 8; c++) {
            unsigned long long w = wr[c];
            fma2(acc0[c], a0, w);
            fma2(acc1[c], a1, w);
        }
    }

    // epilogue: combine halves, leaky, l2-norm (8 threads share a node), store fp32+fp16
    const unsigned mask = 0xffffffffu;
#pragma unroll
    for (int j = 0; j < 2; j++) {
        int gn = base + n0 + j;
        unsigned long long* accj = (j == 0) ? acc0 : acc1;
        float o[8];
        float s = 0.f;
#pragma unroll
        for (int c = 0; c < 8; c++) {
            float2 t = upk2(accj[c]);
            float v = t.x + t.y;
            v = (v >= 0.f) ? v : NEG_SLOPE * v;
            o[c] = v;
            s += v * v;
        }
        s += __shfl_xor_sync(mask, s, 1, 8);
        s += __shfl_xor_sync(mask, s, 2, 8);
        s += __shfl_xor_sync(mask, s, 4, 8);
        float sc = 1.0f / fmaxf(sqrtf(s), 1e-12f);

        if (gn < N_NODESC) {
            float4 v0 = make_float4(o[0] * sc, o[1] * sc, o[2] * sc, o[3] * sc);
            float4 v1 = make_float4(o[4] * sc, o[5] * sc, o[6] * sc, o[7] * sc);
            float4* outr = reinterpret_cast<float4*>(g_ego + gn * EMB + c0);
            outr[0] = v0;
            outr[1] = v1;
            __half2 h0 = __float22half2_rn(make_float2(v0.x, v0.y));
            __half2 h1 = __float22half2_rn(make_float2(v0.z, v0.w));
            __half2 h2 = __float22half2_rn(make_float2(v1.x, v1.y));
            __half2 h3 = __float22half2_rn(make_float2(v1.z, v1.w));
            uint4 hp;
            hp.x = *reinterpret_cast<unsigned*>(&h0);
            hp.y = *reinterpret_cast<unsigned*>(&h1);
            hp.z = *reinterpret_cast<unsigned*>(&h2);
            hp.w = *reinterpret_cast<unsigned*>(&h3);
            *reinterpret_cast<uint4*>(reinterpret_cast<char*>(g_egoH) + gn * 128 + g_c * 16) = hp;
        }
    }
}

// ---------------- output gather for one stage ----------------
__global__ void gather_out_kernel(const int* __restrict__ users,
                                  const int* __restrict__ pos,
                                  const int* __restrict__ neg,
                                  float* __restrict__ out,
                                  int stage) {
    int gid = blockIdx.x * blockDim.x + threadIdx.x;
    int r = gid >> 4;
    if (r >= 3 * BATCHC) return;
    int g = gid & 15;
    int node;
    if (r < BATCHC) node = users[r];
    else if (r < 2 * BATCHC) node = N_USERS + pos[r - BATCHC];
    else node = N_USERS + neg[r - 2 * BATCHC];

    const float4* ego4 = reinterpret_cast<const float4*>(g_ego);
    float4 v = ego4[node * 16 + g];
    *reinterpret_cast<float4*>(&out[(size_t)r * (4 * EMB) + stage * EMB + g * 4]) = v;
}

// ---------------- launch ----------------
extern "C" void kernel_launch(void* const* d_in, const int* in_sizes, int n_in,
                              void* d_out, int out_size) {
    const int*   edge_row = (const int*)d_in[0];
    const int*   edge_col = (const int*)d_in[1];
    const float* edge_val = (const float*)d_in[2];
    const float* user_emb = (const float*)d_in[3];
    const float* item_emb = (const float*)d_in[4];
    const float* W_gc     = (const float*)d_in[5];
    const float* b_gc     = (const float*)d_in[6];
    const float* W_bi     = (const float*)d_in[7];
    const float* b_bi     = (const float*)d_in[8];
    const int*   users    = (const int*)d_in[9];
    const int*   pos      = (const int*)d_in[10];
    const int*   neg      = (const int*)d_in[11];
    float* out = (float*)d_out;

    const int T = 256;
    const int nbNodes = (N_NODESC + T - 1) / T;
    const int nbEdges = (N_EDGESC + T - 1) / T;
    const int scanBlocks = (N_NODESC + 1023) / 1024;   // 293
    const int nbNode16 = (N_NODESC * 16) / T;          // 18750 (exact)
    const int nbGather = (3 * BATCHC * 16 + T - 1) / T;
    const int nbTrans = (N_NODESC + TN - 1) / TN;      // 4688

    // dynamic smem for transform: sPx + sWc + sb
    const int smemBytes = TN * SPX_STRIDE * 8 + 8 * WCH_STRIDE * 8 + EMB * 4;  // ~67 KB
    cudaFuncSetAttribute(transform_kernel, cudaFuncAttributeMaxDynamicSharedMemorySize,
                         smemBytes);

    // CSR build
    zero_cnt_kernel<<<nbNodes, T>>>();
    hist_kernel<<<nbEdges, T>>>(edge_row);
    scan1_kernel<<<scanBlocks, 1024>>>();
    scan2_kernel<<<1, 512>>>(scanBlocks);
    scan3_kernel<<<nbNodes, T>>>();
    scatter_kernel<<<nbEdges, T>>>(edge_row, edge_col, edge_val);

    // init ego (fp32 + fp16 mirror)
    copy_ego_kernel<<<nbNode16, T>>>((const float4*)user_emb, (const float4*)item_emb);

    // stage 0 output
    gather_out_kernel<<<nbGather, T>>>(users, pos, neg, out, 0);

    // 3 layers
    for (int k = 0; k < NLAYERS; k++) {
        aggregate_kernel<<<nbNode16, T>>>();
        transform_kernel<<<nbTrans, TTHREADS, smemBytes>>>(W_gc, b_gc, W_bi, b_bi, k);
        gather_out_kernel<<<nbGather, T>>>(users, pos, neg, out, k + 1);
    }
}